// round 11
// baseline (speedup 1.0000x reference)
#include <cuda_runtime.h>
#include <cuda_fp16.h>
#include <cstdint>
#include <cstddef>

#define TOKENS 8192
#define HDIM 1024
#define FFDIM 4096
#define NEXP 8
#define SLOTS (TOKENS*2)
#define RBLOCKS (TOKENS/8)

// ---------------- scratch (device globals; no allocation allowed) ----------------
__device__ __half g_Xh[(size_t)TOKENS * HDIM];          // 16 MB  fp16 x
__device__ __half g_WgT[(size_t)NEXP * FFDIM * HDIM];   // 64 MB  w_gate^T [e][ff][h] fp16
__device__ __half g_WuT[(size_t)NEXP * FFDIM * HDIM];   // 64 MB  w_up^T
__device__ __half g_WdT[(size_t)NEXP * HDIM * FFDIM];   // 64 MB  w_down^T [e][h][ff]
__device__ __half g_Hh[(size_t)SLOTS * FFDIM];          // 128 MB fp16 silu(gate)*up
__device__ float  g_O[(size_t)SLOTS * HDIM];            // 64 MB  per-slot output (fp32)
__device__ int    g_perm[SLOTS];
__device__ int    g_slot_of[TOKENS*2];
__device__ float  g_score[TOKENS*2];
__device__ int    g_eidx[TOKENS*2];
__device__ int    g_offsets[NEXP+1];
__device__ float  g_zpart[RBLOCKS];
__device__ float  g_ppart[RBLOCKS*NEXP];

// ---------------- helpers ----------------
__device__ __forceinline__ void mma_f16(float c[4], const uint32_t a[4], const uint32_t b0,
                                        const uint32_t b1) {
    asm volatile(
        "mma.sync.aligned.m16n8k16.row.col.f32.f16.f16.f32 "
        "{%0,%1,%2,%3}, {%4,%5,%6,%7}, {%8,%9}, {%0,%1,%2,%3};\n"
        : "+f"(c[0]), "+f"(c[1]), "+f"(c[2]), "+f"(c[3])
        : "r"(a[0]), "r"(a[1]), "r"(a[2]), "r"(a[3]), "r"(b0), "r"(b1));
}
__device__ __forceinline__ void ldsm4(uint32_t r[4], uint32_t addr) {
    asm volatile("ldmatrix.sync.aligned.m8n8.x4.shared.b16 {%0,%1,%2,%3}, [%4];"
                 : "=r"(r[0]), "=r"(r[1]), "=r"(r[2]), "=r"(r[3]) : "r"(addr));
}
__device__ __forceinline__ void cpa16(uint32_t saddr, const void* gsrc, int srcbytes) {
    asm volatile("cp.async.cg.shared.global [%0], [%1], 16, %2;\n"
                 :: "r"(saddr), "l"(gsrc), "r"(srcbytes));
}
__device__ __forceinline__ void cpa_commit() {
    asm volatile("cp.async.commit_group;\n" ::: "memory");
}
template <int N>
__device__ __forceinline__ void cpa_wait() {
    asm volatile("cp.async.wait_group %0;\n" :: "n"(N) : "memory");
}
__device__ __forceinline__ uint32_t smem_u32(const void* p) {
    return (uint32_t)__cvta_generic_to_shared(p);
}

// ---------------- router (fused with x -> fp16 conversion) ----------------
__global__ void router_kernel(const float* __restrict__ x, const float* __restrict__ wr) {
    __shared__ float s_z[8];
    __shared__ float s_p[8][NEXP];
    int warp = threadIdx.x >> 5, lane = threadIdx.x & 31;
    int t = blockIdx.x * 8 + warp;
    const float* xr = x + (size_t)t * HDIM;
    __half* xh = g_Xh + (size_t)t * HDIM;
    float acc[NEXP];
#pragma unroll
    for (int e = 0; e < NEXP; e++) acc[e] = 0.f;
    for (int i = lane; i < HDIM; i += 32) {
        float xv = xr[i];
        xh[i] = __float2half_rn(xv);
        const float4* w4 = reinterpret_cast<const float4*>(wr + (size_t)i * NEXP);
        float4 w0 = w4[0], w1 = w4[1];
        acc[0] += xv * w0.x; acc[1] += xv * w0.y; acc[2] += xv * w0.z; acc[3] += xv * w0.w;
        acc[4] += xv * w1.x; acc[5] += xv * w1.y; acc[6] += xv * w1.z; acc[7] += xv * w1.w;
    }
#pragma unroll
    for (int e = 0; e < NEXP; e++)
#pragma unroll
        for (int o = 16; o > 0; o >>= 1) acc[e] += __shfl_xor_sync(0xffffffffu, acc[e], o);

    if (lane == 0) {
        float z = 0.f, mx = acc[0];
#pragma unroll
        for (int e = 0; e < NEXP; e++) { z += acc[e] * acc[e]; mx = fmaxf(mx, acc[e]); }
        float p[NEXP], s = 0.f;
#pragma unroll
        for (int e = 0; e < NEXP; e++) { p[e] = expf(acc[e] - mx); s += p[e]; }
        float inv = 1.f / s;
#pragma unroll
        for (int e = 0; e < NEXP; e++) p[e] *= inv;
        int i0 = 0;
#pragma unroll
        for (int e = 1; e < NEXP; e++) if (p[e] > p[i0]) i0 = e;
        int i1 = (i0 == 0) ? 1 : 0;
#pragma unroll
        for (int e = 0; e < NEXP; e++) if (e != i0 && p[e] > p[i1]) i1 = e;
        float s0 = p[i0], s1 = p[i1], sn = 1.f / (s0 + s1);
        g_eidx[t*2] = i0;  g_eidx[t*2+1] = i1;
        g_score[t*2] = s0 * sn; g_score[t*2+1] = s1 * sn;
        s_z[warp] = z;
#pragma unroll
        for (int e = 0; e < NEXP; e++) s_p[warp][e] = p[e];
    }
    __syncthreads();
    if (threadIdx.x == 0) {
        float z = 0.f;
#pragma unroll
        for (int w = 0; w < 8; w++) z += s_z[w];
        g_zpart[blockIdx.x] = z;
    }
    if (threadIdx.x < NEXP) {
        float ps = 0.f;
#pragma unroll
        for (int w = 0; w < 8; w++) ps += s_p[w][threadIdx.x];
        g_ppart[blockIdx.x * NEXP + threadIdx.x] = ps;
    }
}

// ---------------- fused count + scan + scatter (single block) ----------------
__global__ void route_kernel() {
    __shared__ int s_cnt[NEXP];
    __shared__ int s_cur[NEXP];
    int tid = threadIdx.x;                 // 1024 threads
    if (tid < NEXP) s_cnt[tid] = 0;
    __syncthreads();
    for (int i = tid; i < TOKENS*2; i += 1024)
        atomicAdd(&s_cnt[g_eidx[i]], 1);
    __syncthreads();
    if (tid == 0) {
        int o = 0;
        for (int e = 0; e < NEXP; e++) { g_offsets[e] = o; s_cur[e] = o; o += s_cnt[e]; }
        g_offsets[NEXP] = o;
    }
    __syncthreads();
    for (int i = tid; i < TOKENS*2; i += 1024) {
        int e = g_eidx[i];
        int pos = atomicAdd(&s_cur[e], 1);
        g_perm[pos] = i >> 1;
        g_slot_of[i] = pos;
    }
}

// ---------------- convert + transpose all 3 weights to fp16 [e][n][k] --------------
__global__ void convert_w_kernel(const float* __restrict__ w_gate,
                                 const float* __restrict__ w_up,
                                 const float* __restrict__ w_down) {
    __shared__ float tile[64][33];
    const int kind = blockIdx.z >> 3;
    const int e = blockIdx.z & 7;
    const int R = (kind < 2) ? HDIM : FFDIM;
    const int C = (kind < 2) ? FFDIM : HDIM;
    const int tilesC = C / 32;
    const int tr = blockIdx.x / tilesC, tc = blockIdx.x % tilesC;
    const int r0 = tr * 64, c0 = tc * 32;
    const float* src = ((kind == 0) ? w_gate : (kind == 1) ? w_up : w_down) + (size_t)e * R * C;
    __half2* dst = reinterpret_cast<__half2*>(
        ((kind == 0) ? g_WgT : (kind == 1) ? g_WuT : g_WdT) + (size_t)e * R * C);

    const int tx = threadIdx.x, ty = threadIdx.y;   // (32, 8)
#pragma unroll
    for (int i = ty; i < 64; i += 8)
        tile[i][tx] = src[(size_t)(r0 + i) * C + c0 + tx];
    __syncthreads();
#pragma unroll
    for (int i = ty; i < 32; i += 8) {
        int c = c0 + i;
        __half2 v = __floats2half2_rn(tile[2*tx][i], tile[2*tx + 1][i]);
        dst[((size_t)c * R + r0) / 2 + tx] = v;
    }
}

// =======================================================================================
// GEMM1 (fp16 + ldmatrix + BK=64 + single barrier + prefetch-at-head)
// H = silu(X@Wg) * (X@Wu).  BM=128, BN=64/matrix, BK=64. 256 threads, warps 2Mx4N.
// Stage = A 128x36 + Bg 64x36 + Bu 64x36 = 9216 u32 = 36864 B; 3 stages = 110592 B.
// =======================================================================================
#define G1_A (128*36)
#define G1_B (64*36)
#define G1_STG (G1_A + 2*G1_B)          // 9216 u32
#define G1_SMEM (3 * G1_STG * 4)        // 110592 B
__global__ __launch_bounds__(256, 2) void gemm1_kernel() {
    const int e = blockIdx.z;
    const int off = g_offsets[e];
    const int cnt = g_offsets[e+1] - off;
    const int m0 = blockIdx.y * 128;
    if (m0 >= cnt) return;
    const int n0 = blockIdx.x * 64;

    extern __shared__ uint32_t smem[];
    const uint32_t sb0 = smem_u32(smem);

    const int tid = threadIdx.x, lane = tid & 31, wid = tid >> 5;
    const int wm = (wid & 1) * 64, wn = (wid >> 1) * 16;

    // ldmatrix fragment addresses (byte offsets within a stage)
    const uint32_t afrag = sb0 + ((wm + (lane & 15)) * 36 + ((lane >> 4) << 2)) * 4;
    const int bfrow = ((lane >> 4) << 3) + (lane & 7);
    const uint32_t bfcol = ((lane >> 3) & 1) << 2;
    const uint32_t gfrag = sb0 + (G1_A + (wn + bfrow) * 36 + bfcol) * 4;
    const uint32_t ufrag = gfrag + G1_B * 4;

    // cp.async: A 128 rows x 8 chunks = 1024 -> 4/thread
    const int ac = tid & 7;
    const int ar = tid >> 3;
    const __half* aptr[4]; int avalid[4];
#pragma unroll
    for (int i = 0; i < 4; i++) {
        int m = m0 + ar + i * 32;
        avalid[i] = (m < cnt) ? 16 : 0;
        aptr[i] = (m < cnt) ? (g_Xh + (size_t)g_perm[off + m] * HDIM + ac * 8) : g_Xh;
    }
    const uint32_t a_dst0 = sb0 + (ar*36 + ac*4) * 4;
    const __half* gptr = g_WgT + ((size_t)e * FFDIM + n0 + ar) * HDIM + ac * 8;
    const __half* uptr = g_WuT + ((size_t)e * FFDIM + n0 + ar) * HDIM + ac * 8;
    const uint32_t g_dst0 = sb0 + (G1_A + ar*36 + ac*4) * 4;
    const uint32_t u_dst0 = g_dst0 + G1_B * 4;

    float cg[4][2][4], cu[4][2][4];
#pragma unroll
    for (int mi = 0; mi < 4; mi++)
#pragma unroll
        for (int ni = 0; ni < 2; ni++)
#pragma unroll
            for (int j = 0; j < 4; j++) { cg[mi][ni][j] = 0.f; cu[mi][ni][j] = 0.f; }

    const int NSTEP = HDIM / 64;   // 16

#pragma unroll
    for (int p = 0; p < 2; p++) {
        const uint32_t so = p * G1_STG * 4;
        const int k0 = p * 64;
#pragma unroll
        for (int i = 0; i < 4; i++) cpa16(a_dst0 + i*4608 + so, aptr[i] + k0, avalid[i]);
#pragma unroll
        for (int i = 0; i < 2; i++) {
            cpa16(g_dst0 + i*4608 + so, gptr + (size_t)(i*32) * HDIM + k0, 16);
            cpa16(u_dst0 + i*4608 + so, uptr + (size_t)(i*32) * HDIM + k0, 16);
        }
        cpa_commit();
    }

    int cur = 0;
    for (int s = 0; s < NSTEP; s++) {
        if (s + 1 < NSTEP) cpa_wait<1>(); else cpa_wait<0>();
        __syncthreads();

        // prefetch-at-head: target stage (s+2)%3 == (s-1)%3, last read at step s-1,
        // all readers passed this step's barrier -> race-free. Longer copy flight time.
        if (s + 2 < NSTEP) {
            const uint32_t po = ((s + 2) % 3) * G1_STG * 4;
            const int k0 = (s + 2) * 64;
#pragma unroll
            for (int i = 0; i < 4; i++) cpa16(a_dst0 + i*4608 + po, aptr[i] + k0, avalid[i]);
#pragma unroll
            for (int i = 0; i < 2; i++) {
                cpa16(g_dst0 + i*4608 + po, gptr + (size_t)(i*32) * HDIM + k0, 16);
                cpa16(u_dst0 + i*4608 + po, uptr + (size_t)(i*32) * HDIM + k0, 16);
            }
        }
        cpa_commit();

        const uint32_t so = cur * G1_STG * 4;
#pragma unroll
        for (int kk = 0; kk < 4; kk++) {
            uint32_t a[4][4], bg[4], bu[4];
#pragma unroll
            for (int mi = 0; mi < 4; mi++)
                ldsm4(a[mi], afrag + so + mi * 2304 + kk * 32);
            ldsm4(bg, gfrag + so + kk * 32);
            ldsm4(bu, ufrag + so + kk * 32);
#pragma unroll
            for (int mi = 0; mi < 4; mi++) {
                mma_f16(cg[mi][0], a[mi], bg[0], bg[1]);
                mma_f16(cg[mi][1], a[mi], bg[2], bg[3]);
                mma_f16(cu[mi][0], a[mi], bu[0], bu[1]);
                mma_f16(cu[mi][1], a[mi], bu[2], bu[3]);
            }
        }
        cur = (cur + 1) % 3;
    }

    // epilogue: silu(g)*u -> fp16 H
    const int fr = lane >> 2, fc2 = (lane & 3) * 2;
    __half2* H2 = reinterpret_cast<__half2*>(g_Hh);
#pragma unroll
    for (int mi = 0; mi < 4; mi++) {
        int r1 = wm + mi * 16 + fr;
        int m1 = m0 + r1, m2 = m1 + 8;
#pragma unroll
        for (int ni = 0; ni < 2; ni++) {
            int col = n0 + wn + ni * 8 + fc2;
            if (m1 < cnt) {
                float g0 = cg[mi][ni][0], g1 = cg[mi][ni][1];
                float u0 = cu[mi][ni][0], u1 = cu[mi][ni][1];
                float h0 = g0 / (1.f + expf(-g0)) * u0;
                float h1 = g1 / (1.f + expf(-g1)) * u1;
                H2[((size_t)(off+m1) * FFDIM + col) / 2] = __floats2half2_rn(h0, h1);
            }
            if (m2 < cnt) {
                float g0 = cg[mi][ni][2], g1 = cg[mi][ni][3];
                float u0 = cu[mi][ni][2], u1 = cu[mi][ni][3];
                float h0 = g0 / (1.f + expf(-g0)) * u0;
                float h1 = g1 / (1.f + expf(-g1)) * u1;
                H2[((size_t)(off+m2) * FFDIM + col) / 2] = __floats2half2_rn(h0, h1);
            }
        }
    }
}

// =======================================================================================
// GEMM2 (fp16 + ldmatrix + BK=64 + single barrier + prefetch-at-head)
// O = H @ Wd^T-layout.  BM=128, BN=128, BK=64. 256 threads, warps 2Mx4N.
// =======================================================================================
#define G2_A (128*36)
#define G2_B (128*36)
#define G2_STG (G2_A + G2_B)            // 9216 u32
#define G2_SMEM (3 * G2_STG * 4)        // 110592 B
__global__ __launch_bounds__(256, 2) void gemm2_kernel() {
    const int e = blockIdx.z;
    const int off = g_offsets[e];
    const int cnt = g_offsets[e+1] - off;
    const int m0 = blockIdx.y * 128;
    if (m0 >= cnt) return;
    const int n0 = blockIdx.x * 128;

    extern __shared__ uint32_t smem[];
    const uint32_t sb0 = smem_u32(smem);

    const int tid = threadIdx.x, lane = tid & 31, wid = tid >> 5;
    const int wm = (wid & 1) * 64, wn = (wid >> 1) * 32;

    const uint32_t afrag = sb0 + ((wm + (lane & 15)) * 36 + ((lane >> 4) << 2)) * 4;
    const int bfrow = ((lane >> 4) << 3) + (lane & 7);
    const uint32_t bfcol = ((lane >> 3) & 1) << 2;
    const uint32_t bfrag = sb0 + (G2_A + (wn + bfrow) * 36 + bfcol) * 4;

    const int ac = tid & 7;
    const int ar = tid >> 3;
    const __half* aptr[4]; int avalid[4];
#pragma unroll
    for (int i = 0; i < 4; i++) {
        int m = m0 + ar + i * 32;
        avalid[i] = (m < cnt) ? 16 : 0;
        aptr[i] = (m < cnt) ? (g_Hh + (size_t)(off + m) * FFDIM + ac * 8) : g_Hh;
    }
    const uint32_t a_dst0 = sb0 + (ar*36 + ac*4) * 4;
    const __half* bptr = g_WdT + ((size_t)e * HDIM + n0 + ar) * FFDIM + ac * 8;
    const uint32_t b_dst0 = sb0 + (G2_A + ar*36 + ac*4) * 4;

    float c[4][4][4];
#pragma unroll
    for (int mi = 0; mi < 4; mi++)
#pragma unroll
        for (int ni = 0; ni < 4; ni++)
#pragma unroll
            for (int j = 0; j < 4; j++) c[mi][ni][j] = 0.f;

    const int NSTEP = FFDIM / 64;  // 64

#pragma unroll
    for (int p = 0; p < 2; p++) {
        const uint32_t so = p * G2_STG * 4;
        const int k0 = p * 64;
#pragma unroll
        for (int i = 0; i < 4; i++) cpa16(a_dst0 + i*4608 + so, aptr[i] + k0, avalid[i]);
#pragma unroll
        for (int i = 0; i < 4; i++)
            cpa16(b_dst0 + i*4608 + so, bptr + (size_t)(i*32) * FFDIM + k0, 16);
        cpa_commit();
    }

    int cur = 0;
    for (int s = 0; s < NSTEP; s++) {
        if (s + 1 < NSTEP) cpa_wait<1>(); else cpa_wait<0>();
        __syncthreads();

        if (s + 2 < NSTEP) {
            const uint32_t po = ((s + 2) % 3) * G2_STG * 4;
            const int k0 = (s + 2) * 64;
#pragma unroll
            for (int i = 0; i < 4; i++) cpa16(a_dst0 + i*4608 + po, aptr[i] + k0, avalid[i]);
#pragma unroll
            for (int i = 0; i < 4; i++)
                cpa16(b_dst0 + i*4608 + po, bptr + (size_t)(i*32) * FFDIM + k0, 16);
        }
        cpa_commit();

        const uint32_t so = cur * G2_STG * 4;
#pragma unroll
        for (int kk = 0; kk < 4; kk++) {
            uint32_t a[4][4], b[2][4];
#pragma unroll
            for (int mi = 0; mi < 4; mi++)
                ldsm4(a[mi], afrag + so + mi * 2304 + kk * 32);
            ldsm4(b[0], bfrag + so + kk * 32);                 // n-tiles 0,1
            ldsm4(b[1], bfrag + so + 2304 + kk * 32);          // n-tiles 2,3 (+16 rows)
#pragma unroll
            for (int mi = 0; mi < 4; mi++) {
                mma_f16(c[mi][0], a[mi], b[0][0], b[0][1]);
                mma_f16(c[mi][1], a[mi], b[0][2], b[0][3]);
                mma_f16(c[mi][2], a[mi], b[1][0], b[1][1]);
                mma_f16(c[mi][3], a[mi], b[1][2], b[1][3]);
            }
        }
        cur = (cur + 1) % 3;
    }

    const int fr = lane >> 2, fc2 = (lane & 3) * 2;
#pragma unroll
    for (int mi = 0; mi < 4; mi++) {
        int r1 = wm + mi * 16 + fr;
        int m1 = m0 + r1, m2 = m1 + 8;
#pragma unroll
        for (int ni = 0; ni < 4; ni++) {
            int col = n0 + wn + ni * 8 + fc2;
            if (m1 < cnt)
                *reinterpret_cast<float2*>(&g_O[(size_t)(off+m1) * HDIM + col]) =
                    make_float2(c[mi][ni][0], c[mi][ni][1]);
            if (m2 < cnt)
                *reinterpret_cast<float2*>(&g_O[(size_t)(off+m2) * HDIM + col]) =
                    make_float2(c[mi][ni][2], c[mi][ni][3]);
        }
    }
}

// ---------------- combine + losses ----------------
__global__ void combine_kernel(float* __restrict__ out) {
    int idx = blockIdx.x * blockDim.x + threadIdx.x;
    int t = idx >> 8;
    int c4 = idx & 255;
    if (t >= TOKENS) return;
    int s0 = g_slot_of[t*2], s1 = g_slot_of[t*2+1];
    float w0 = g_score[t*2], w1 = g_score[t*2+1];
    float4 a = *reinterpret_cast<const float4*>(&g_O[(size_t)s0 * HDIM + c4*4]);
    float4 b = *reinterpret_cast<const float4*>(&g_O[(size_t)s1 * HDIM + c4*4]);
    float4 o;
    o.x = w0*a.x + w1*b.x; o.y = w0*a.y + w1*b.y;
    o.z = w0*a.z + w1*b.z; o.w = w0*a.w + w1*b.w;
    *reinterpret_cast<float4*>(&out[(size_t)t * HDIM + c4*4]) = o;
}

__global__ void loss_kernel(float* __restrict__ out) {
    int lane = threadIdx.x;
    float z = 0.f, pe[NEXP];
#pragma unroll
    for (int e = 0; e < NEXP; e++) pe[e] = 0.f;
    for (int i = lane; i < RBLOCKS; i += 32) {
        z += g_zpart[i];
#pragma unroll
        for (int e = 0; e < NEXP; e++) pe[e] += g_ppart[i*NEXP + e];
    }
#pragma unroll
    for (int o = 16; o > 0; o >>= 1) {
        z += __shfl_xor_sync(0xffffffffu, z, o);
#pragma unroll
        for (int e = 0; e < NEXP; e++) pe[e] += __shfl_xor_sync(0xffffffffu, pe[e], o);
    }
    if (lane == 0) {
        float zl = (float)NEXP * (z / (float)((size_t)TOKENS * NEXP));
        float aux = 0.f;
#pragma unroll
        for (int e = 0; e < NEXP; e++) {
            float pm = pe[e] / (float)TOKENS;
            aux += pm * logf(pm + 1e-9f);
        }
        out[(size_t)TOKENS * HDIM    ] = zl;
        out[(size_t)TOKENS * HDIM + 1] = (float)NEXP * aux;
    }
}

// ---------------- launch ----------------
extern "C" void kernel_launch(void* const* d_in, const int* in_sizes, int n_in,
                              void* d_out, int out_size) {
    const float* x        = (const float*)d_in[0];
    const float* w_router = (const float*)d_in[1];
    const float* w_gate   = (const float*)d_in[2];
    const float* w_up     = (const float*)d_in[3];
    const float* w_down   = (const float*)d_in[4];
    float* out = (float*)d_out;

    cudaFuncSetAttribute(gemm1_kernel, cudaFuncAttributeMaxDynamicSharedMemorySize, G1_SMEM);
    cudaFuncSetAttribute(gemm2_kernel, cudaFuncAttributeMaxDynamicSharedMemorySize, G2_SMEM);

    router_kernel<<<RBLOCKS, 256>>>(x, w_router);                               // 1
    route_kernel<<<1, 1024>>>();                                                // 2
    convert_w_kernel<<<dim3(2048, 1, 24), dim3(32, 8)>>>(w_gate, w_up, w_down); // 3
    gemm1_kernel<<<dim3(FFDIM/64, 64, NEXP), 256, G1_SMEM>>>();                 // 4 <- profiled
    gemm2_kernel<<<dim3(HDIM/128, 64, NEXP), 256, G2_SMEM>>>();                 // 5
    combine_kernel<<<(TOKENS*256)/256, 256>>>(out);                             // 6
    loss_kernel<<<1, 32>>>(out);                                                // 7
}

// round 12
// speedup vs baseline: 1.1360x; 1.1360x over previous
#include <cuda_runtime.h>
#include <cuda_fp16.h>
#include <cstdint>
#include <cstddef>

#define TOKENS 8192
#define HDIM 1024
#define FFDIM 4096
#define NEXP 8
#define SLOTS (TOKENS*2)
#define RBLOCKS (TOKENS/8)

// ---------------- scratch (device globals; no allocation allowed) ----------------
__device__ __half g_Xh[(size_t)TOKENS * HDIM];          // 16 MB  fp16 x
__device__ __half g_WgT[(size_t)NEXP * FFDIM * HDIM];   // 64 MB  w_gate^T [e][ff][h] fp16
__device__ __half g_WuT[(size_t)NEXP * FFDIM * HDIM];   // 64 MB  w_up^T
__device__ __half g_WdT[(size_t)NEXP * HDIM * FFDIM];   // 64 MB  w_down^T [e][h][ff]
__device__ __half g_Hh[(size_t)SLOTS * FFDIM];          // 128 MB fp16 silu(gate)*up
__device__ float  g_O[(size_t)SLOTS * HDIM];            // 64 MB  per-slot output (fp32)
__device__ int    g_perm[SLOTS];
__device__ int    g_slot_of[TOKENS*2];
__device__ float  g_score[TOKENS*2];
__device__ int    g_eidx[TOKENS*2];
__device__ int    g_offsets[NEXP+1];
__device__ float  g_zpart[RBLOCKS];
__device__ float  g_ppart[RBLOCKS*NEXP];

// ---------------- helpers ----------------
__device__ __forceinline__ void mma_f16(float c[4], const uint32_t a[4], const uint32_t b0,
                                        const uint32_t b1) {
    asm volatile(
        "mma.sync.aligned.m16n8k16.row.col.f32.f16.f16.f32 "
        "{%0,%1,%2,%3}, {%4,%5,%6,%7}, {%8,%9}, {%0,%1,%2,%3};\n"
        : "+f"(c[0]), "+f"(c[1]), "+f"(c[2]), "+f"(c[3])
        : "r"(a[0]), "r"(a[1]), "r"(a[2]), "r"(a[3]), "r"(b0), "r"(b1));
}
__device__ __forceinline__ void ldsm4(uint32_t r[4], uint32_t addr) {
    asm volatile("ldmatrix.sync.aligned.m8n8.x4.shared.b16 {%0,%1,%2,%3}, [%4];"
                 : "=r"(r[0]), "=r"(r[1]), "=r"(r[2]), "=r"(r[3]) : "r"(addr));
}
__device__ __forceinline__ void cpa16(uint32_t saddr, const void* gsrc, int srcbytes) {
    asm volatile("cp.async.cg.shared.global [%0], [%1], 16, %2;\n"
                 :: "r"(saddr), "l"(gsrc), "r"(srcbytes));
}
__device__ __forceinline__ void cpa_commit() {
    asm volatile("cp.async.commit_group;\n" ::: "memory");
}
template <int N>
__device__ __forceinline__ void cpa_wait() {
    asm volatile("cp.async.wait_group %0;\n" :: "n"(N) : "memory");
}
__device__ __forceinline__ uint32_t smem_u32(const void* p) {
    return (uint32_t)__cvta_generic_to_shared(p);
}

// ---------------- router (fused with x -> fp16 conversion) ----------------
__global__ void router_kernel(const float* __restrict__ x, const float* __restrict__ wr) {
    __shared__ float s_z[8];
    __shared__ float s_p[8][NEXP];
    int warp = threadIdx.x >> 5, lane = threadIdx.x & 31;
    int t = blockIdx.x * 8 + warp;
    const float* xr = x + (size_t)t * HDIM;
    __half* xh = g_Xh + (size_t)t * HDIM;
    float acc[NEXP];
#pragma unroll
    for (int e = 0; e < NEXP; e++) acc[e] = 0.f;
    for (int i = lane; i < HDIM; i += 32) {
        float xv = xr[i];
        xh[i] = __float2half_rn(xv);
        const float4* w4 = reinterpret_cast<const float4*>(wr + (size_t)i * NEXP);
        float4 w0 = w4[0], w1 = w4[1];
        acc[0] += xv * w0.x; acc[1] += xv * w0.y; acc[2] += xv * w0.z; acc[3] += xv * w0.w;
        acc[4] += xv * w1.x; acc[5] += xv * w1.y; acc[6] += xv * w1.z; acc[7] += xv * w1.w;
    }
#pragma unroll
    for (int e = 0; e < NEXP; e++)
#pragma unroll
        for (int o = 16; o > 0; o >>= 1) acc[e] += __shfl_xor_sync(0xffffffffu, acc[e], o);

    if (lane == 0) {
        float z = 0.f, mx = acc[0];
#pragma unroll
        for (int e = 0; e < NEXP; e++) { z += acc[e] * acc[e]; mx = fmaxf(mx, acc[e]); }
        float p[NEXP], s = 0.f;
#pragma unroll
        for (int e = 0; e < NEXP; e++) { p[e] = expf(acc[e] - mx); s += p[e]; }
        float inv = 1.f / s;
#pragma unroll
        for (int e = 0; e < NEXP; e++) p[e] *= inv;
        int i0 = 0;
#pragma unroll
        for (int e = 1; e < NEXP; e++) if (p[e] > p[i0]) i0 = e;
        int i1 = (i0 == 0) ? 1 : 0;
#pragma unroll
        for (int e = 0; e < NEXP; e++) if (e != i0 && p[e] > p[i1]) i1 = e;
        float s0 = p[i0], s1 = p[i1], sn = 1.f / (s0 + s1);
        g_eidx[t*2] = i0;  g_eidx[t*2+1] = i1;
        g_score[t*2] = s0 * sn; g_score[t*2+1] = s1 * sn;
        s_z[warp] = z;
#pragma unroll
        for (int e = 0; e < NEXP; e++) s_p[warp][e] = p[e];
    }
    __syncthreads();
    if (threadIdx.x == 0) {
        float z = 0.f;
#pragma unroll
        for (int w = 0; w < 8; w++) z += s_z[w];
        g_zpart[blockIdx.x] = z;
    }
    if (threadIdx.x < NEXP) {
        float ps = 0.f;
#pragma unroll
        for (int w = 0; w < 8; w++) ps += s_p[w][threadIdx.x];
        g_ppart[blockIdx.x * NEXP + threadIdx.x] = ps;
    }
}

// ---------------- fused count + scan + scatter (single block) ----------------
__global__ void route_kernel() {
    __shared__ int s_cnt[NEXP];
    __shared__ int s_cur[NEXP];
    int tid = threadIdx.x;                 // 1024 threads
    if (tid < NEXP) s_cnt[tid] = 0;
    __syncthreads();
    for (int i = tid; i < TOKENS*2; i += 1024)
        atomicAdd(&s_cnt[g_eidx[i]], 1);
    __syncthreads();
    if (tid == 0) {
        int o = 0;
        for (int e = 0; e < NEXP; e++) { g_offsets[e] = o; s_cur[e] = o; o += s_cnt[e]; }
        g_offsets[NEXP] = o;
    }
    __syncthreads();
    for (int i = tid; i < TOKENS*2; i += 1024) {
        int e = g_eidx[i];
        int pos = atomicAdd(&s_cur[e], 1);
        g_perm[pos] = i >> 1;
        g_slot_of[i] = pos;
    }
}

// ---------------- convert + transpose all 3 weights to fp16 [e][n][k] --------------
__global__ void convert_w_kernel(const float* __restrict__ w_gate,
                                 const float* __restrict__ w_up,
                                 const float* __restrict__ w_down) {
    __shared__ float tile[64][33];
    const int kind = blockIdx.z >> 3;
    const int e = blockIdx.z & 7;
    const int R = (kind < 2) ? HDIM : FFDIM;
    const int C = (kind < 2) ? FFDIM : HDIM;
    const int tilesC = C / 32;
    const int tr = blockIdx.x / tilesC, tc = blockIdx.x % tilesC;
    const int r0 = tr * 64, c0 = tc * 32;
    const float* src = ((kind == 0) ? w_gate : (kind == 1) ? w_up : w_down) + (size_t)e * R * C;
    __half2* dst = reinterpret_cast<__half2*>(
        ((kind == 0) ? g_WgT : (kind == 1) ? g_WuT : g_WdT) + (size_t)e * R * C);

    const int tx = threadIdx.x, ty = threadIdx.y;   // (32, 8)
#pragma unroll
    for (int i = ty; i < 64; i += 8)
        tile[i][tx] = src[(size_t)(r0 + i) * C + c0 + tx];
    __syncthreads();
#pragma unroll
    for (int i = ty; i < 32; i += 8) {
        int c = c0 + i;
        __half2 v = __floats2half2_rn(tile[2*tx][i], tile[2*tx + 1][i]);
        dst[((size_t)c * R + r0) / 2 + tx] = v;
    }
}

// =======================================================================================
// GEMM1 (fp16 + ldmatrix + BK=64 + single barrier + MID-LOOP prefetch)
// H = silu(X@Wg) * (X@Wu).  BM=128, BN=64/matrix, BK=64. 256 threads, warps 2Mx4N.
// Stage = A 128x36 + Bg 64x36 + Bu 64x36 = 9216 u32 = 36864 B; 3 stages = 110592 B.
// =======================================================================================
#define G1_A (128*36)
#define G1_B (64*36)
#define G1_STG (G1_A + 2*G1_B)          // 9216 u32
#define G1_SMEM (3 * G1_STG * 4)        // 110592 B
__global__ __launch_bounds__(256, 2) void gemm1_kernel() {
    const int e = blockIdx.z;
    const int off = g_offsets[e];
    const int cnt = g_offsets[e+1] - off;
    const int m0 = blockIdx.y * 128;
    if (m0 >= cnt) return;
    const int n0 = blockIdx.x * 64;

    extern __shared__ uint32_t smem[];
    const uint32_t sb0 = smem_u32(smem);

    const int tid = threadIdx.x, lane = tid & 31, wid = tid >> 5;
    const int wm = (wid & 1) * 64, wn = (wid >> 1) * 16;

    // ldmatrix fragment addresses (byte offsets within a stage)
    const uint32_t afrag = sb0 + ((wm + (lane & 15)) * 36 + ((lane >> 4) << 2)) * 4;
    const int bfrow = ((lane >> 4) << 3) + (lane & 7);
    const uint32_t bfcol = ((lane >> 3) & 1) << 2;
    const uint32_t gfrag = sb0 + (G1_A + (wn + bfrow) * 36 + bfcol) * 4;
    const uint32_t ufrag = gfrag + G1_B * 4;

    // cp.async: A 128 rows x 8 chunks = 1024 -> 4/thread
    const int ac = tid & 7;
    const int ar = tid >> 3;
    const __half* aptr[4]; int avalid[4];
#pragma unroll
    for (int i = 0; i < 4; i++) {
        int m = m0 + ar + i * 32;
        avalid[i] = (m < cnt) ? 16 : 0;
        aptr[i] = (m < cnt) ? (g_Xh + (size_t)g_perm[off + m] * HDIM + ac * 8) : g_Xh;
    }
    const uint32_t a_dst0 = sb0 + (ar*36 + ac*4) * 4;
    const __half* gptr = g_WgT + ((size_t)e * FFDIM + n0 + ar) * HDIM + ac * 8;
    const __half* uptr = g_WuT + ((size_t)e * FFDIM + n0 + ar) * HDIM + ac * 8;
    const uint32_t g_dst0 = sb0 + (G1_A + ar*36 + ac*4) * 4;
    const uint32_t u_dst0 = g_dst0 + G1_B * 4;

    float cg[4][2][4], cu[4][2][4];
#pragma unroll
    for (int mi = 0; mi < 4; mi++)
#pragma unroll
        for (int ni = 0; ni < 2; ni++)
#pragma unroll
            for (int j = 0; j < 4; j++) { cg[mi][ni][j] = 0.f; cu[mi][ni][j] = 0.f; }

    const int NSTEP = HDIM / 64;   // 16

#pragma unroll
    for (int p = 0; p < 2; p++) {
        const uint32_t so = p * G1_STG * 4;
        const int k0 = p * 64;
#pragma unroll
        for (int i = 0; i < 4; i++) cpa16(a_dst0 + i*4608 + so, aptr[i] + k0, avalid[i]);
#pragma unroll
        for (int i = 0; i < 2; i++) {
            cpa16(g_dst0 + i*4608 + so, gptr + (size_t)(i*32) * HDIM + k0, 16);
            cpa16(u_dst0 + i*4608 + so, uptr + (size_t)(i*32) * HDIM + k0, 16);
        }
        cpa_commit();
    }

    int cur = 0;
    for (int s = 0; s < NSTEP; s++) {
        if (s + 1 < NSTEP) cpa_wait<1>(); else cpa_wait<0>();
        __syncthreads();

        const uint32_t so = cur * G1_STG * 4;

        // first half of compute: kk = 0,1 (tensor pipe starts immediately)
#pragma unroll
        for (int kk = 0; kk < 2; kk++) {
            uint32_t a[4][4], bg[4], bu[4];
#pragma unroll
            for (int mi = 0; mi < 4; mi++)
                ldsm4(a[mi], afrag + so + mi * 2304 + kk * 32);
            ldsm4(bg, gfrag + so + kk * 32);
            ldsm4(bu, ufrag + so + kk * 32);
#pragma unroll
            for (int mi = 0; mi < 4; mi++) {
                mma_f16(cg[mi][0], a[mi], bg[0], bg[1]);
                mma_f16(cg[mi][1], a[mi], bg[2], bg[3]);
                mma_f16(cu[mi][0], a[mi], bu[0], bu[1]);
                mma_f16(cu[mi][1], a[mi], bu[2], bu[3]);
            }
        }

        // mid-loop prefetch: target stage (s+2)%3 == (s-1)%3, readers done before this
        // step's barrier -> race-free. Compute already in flight; +0.5 step copy slack.
        if (s + 2 < NSTEP) {
            const uint32_t po = ((s + 2) % 3) * G1_STG * 4;
            const int k0 = (s + 2) * 64;
#pragma unroll
            for (int i = 0; i < 4; i++) cpa16(a_dst0 + i*4608 + po, aptr[i] + k0, avalid[i]);
#pragma unroll
            for (int i = 0; i < 2; i++) {
                cpa16(g_dst0 + i*4608 + po, gptr + (size_t)(i*32) * HDIM + k0, 16);
                cpa16(u_dst0 + i*4608 + po, uptr + (size_t)(i*32) * HDIM + k0, 16);
            }
        }
        cpa_commit();

        // second half of compute: kk = 2,3
#pragma unroll
        for (int kk = 2; kk < 4; kk++) {
            uint32_t a[4][4], bg[4], bu[4];
#pragma unroll
            for (int mi = 0; mi < 4; mi++)
                ldsm4(a[mi], afrag + so + mi * 2304 + kk * 32);
            ldsm4(bg, gfrag + so + kk * 32);
            ldsm4(bu, ufrag + so + kk * 32);
#pragma unroll
            for (int mi = 0; mi < 4; mi++) {
                mma_f16(cg[mi][0], a[mi], bg[0], bg[1]);
                mma_f16(cg[mi][1], a[mi], bg[2], bg[3]);
                mma_f16(cu[mi][0], a[mi], bu[0], bu[1]);
                mma_f16(cu[mi][1], a[mi], bu[2], bu[3]);
            }
        }
        cur = (cur + 1) % 3;
    }

    // epilogue: silu(g)*u -> fp16 H
    const int fr = lane >> 2, fc2 = (lane & 3) * 2;
    __half2* H2 = reinterpret_cast<__half2*>(g_Hh);
#pragma unroll
    for (int mi = 0; mi < 4; mi++) {
        int r1 = wm + mi * 16 + fr;
        int m1 = m0 + r1, m2 = m1 + 8;
#pragma unroll
        for (int ni = 0; ni < 2; ni++) {
            int col = n0 + wn + ni * 8 + fc2;
            if (m1 < cnt) {
                float g0 = cg[mi][ni][0], g1 = cg[mi][ni][1];
                float u0 = cu[mi][ni][0], u1 = cu[mi][ni][1];
                float h0 = g0 / (1.f + expf(-g0)) * u0;
                float h1 = g1 / (1.f + expf(-g1)) * u1;
                H2[((size_t)(off+m1) * FFDIM + col) / 2] = __floats2half2_rn(h0, h1);
            }
            if (m2 < cnt) {
                float g0 = cg[mi][ni][2], g1 = cg[mi][ni][3];
                float u0 = cu[mi][ni][2], u1 = cu[mi][ni][3];
                float h0 = g0 / (1.f + expf(-g0)) * u0;
                float h1 = g1 / (1.f + expf(-g1)) * u1;
                H2[((size_t)(off+m2) * FFDIM + col) / 2] = __floats2half2_rn(h0, h1);
            }
        }
    }
}

// =======================================================================================
// GEMM2 (fp16 + ldmatrix + BK=64 + single barrier + MID-LOOP prefetch)
// O = H @ Wd^T-layout.  BM=128, BN=128, BK=64. 256 threads, warps 2Mx4N.
// =======================================================================================
#define G2_A (128*36)
#define G2_B (128*36)
#define G2_STG (G2_A + G2_B)            // 9216 u32
#define G2_SMEM (3 * G2_STG * 4)        // 110592 B
__global__ __launch_bounds__(256, 2) void gemm2_kernel() {
    const int e = blockIdx.z;
    const int off = g_offsets[e];
    const int cnt = g_offsets[e+1] - off;
    const int m0 = blockIdx.y * 128;
    if (m0 >= cnt) return;
    const int n0 = blockIdx.x * 128;

    extern __shared__ uint32_t smem[];
    const uint32_t sb0 = smem_u32(smem);

    const int tid = threadIdx.x, lane = tid & 31, wid = tid >> 5;
    const int wm = (wid & 1) * 64, wn = (wid >> 1) * 32;

    const uint32_t afrag = sb0 + ((wm + (lane & 15)) * 36 + ((lane >> 4) << 2)) * 4;
    const int bfrow = ((lane >> 4) << 3) + (lane & 7);
    const uint32_t bfcol = ((lane >> 3) & 1) << 2;
    const uint32_t bfrag = sb0 + (G2_A + (wn + bfrow) * 36 + bfcol) * 4;

    const int ac = tid & 7;
    const int ar = tid >> 3;
    const __half* aptr[4]; int avalid[4];
#pragma unroll
    for (int i = 0; i < 4; i++) {
        int m = m0 + ar + i * 32;
        avalid[i] = (m < cnt) ? 16 : 0;
        aptr[i] = (m < cnt) ? (g_Hh + (size_t)(off + m) * FFDIM + ac * 8) : g_Hh;
    }
    const uint32_t a_dst0 = sb0 + (ar*36 + ac*4) * 4;
    const __half* bptr = g_WdT + ((size_t)e * HDIM + n0 + ar) * FFDIM + ac * 8;
    const uint32_t b_dst0 = sb0 + (G2_A + ar*36 + ac*4) * 4;

    float c[4][4][4];
#pragma unroll
    for (int mi = 0; mi < 4; mi++)
#pragma unroll
        for (int ni = 0; ni < 4; ni++)
#pragma unroll
            for (int j = 0; j < 4; j++) c[mi][ni][j] = 0.f;

    const int NSTEP = FFDIM / 64;  // 64

#pragma unroll
    for (int p = 0; p < 2; p++) {
        const uint32_t so = p * G2_STG * 4;
        const int k0 = p * 64;
#pragma unroll
        for (int i = 0; i < 4; i++) cpa16(a_dst0 + i*4608 + so, aptr[i] + k0, avalid[i]);
#pragma unroll
        for (int i = 0; i < 4; i++)
            cpa16(b_dst0 + i*4608 + so, bptr + (size_t)(i*32) * FFDIM + k0, 16);
        cpa_commit();
    }

    int cur = 0;
    for (int s = 0; s < NSTEP; s++) {
        if (s + 1 < NSTEP) cpa_wait<1>(); else cpa_wait<0>();
        __syncthreads();

        const uint32_t so = cur * G2_STG * 4;

#pragma unroll
        for (int kk = 0; kk < 2; kk++) {
            uint32_t a[4][4], b[2][4];
#pragma unroll
            for (int mi = 0; mi < 4; mi++)
                ldsm4(a[mi], afrag + so + mi * 2304 + kk * 32);
            ldsm4(b[0], bfrag + so + kk * 32);
            ldsm4(b[1], bfrag + so + 2304 + kk * 32);
#pragma unroll
            for (int mi = 0; mi < 4; mi++) {
                mma_f16(c[mi][0], a[mi], b[0][0], b[0][1]);
                mma_f16(c[mi][1], a[mi], b[0][2], b[0][3]);
                mma_f16(c[mi][2], a[mi], b[1][0], b[1][1]);
                mma_f16(c[mi][3], a[mi], b[1][2], b[1][3]);
            }
        }

        if (s + 2 < NSTEP) {
            const uint32_t po = ((s + 2) % 3) * G2_STG * 4;
            const int k0 = (s + 2) * 64;
#pragma unroll
            for (int i = 0; i < 4; i++) cpa16(a_dst0 + i*4608 + po, aptr[i] + k0, avalid[i]);
#pragma unroll
            for (int i = 0; i < 4; i++)
                cpa16(b_dst0 + i*4608 + po, bptr + (size_t)(i*32) * FFDIM + k0, 16);
        }
        cpa_commit();

#pragma unroll
        for (int kk = 2; kk < 4; kk++) {
            uint32_t a[4][4], b[2][4];
#pragma unroll
            for (int mi = 0; mi < 4; mi++)
                ldsm4(a[mi], afrag + so + mi * 2304 + kk * 32);
            ldsm4(b[0], bfrag + so + kk * 32);
            ldsm4(b[1], bfrag + so + 2304 + kk * 32);
#pragma unroll
            for (int mi = 0; mi < 4; mi++) {
                mma_f16(c[mi][0], a[mi], b[0][0], b[0][1]);
                mma_f16(c[mi][1], a[mi], b[0][2], b[0][3]);
                mma_f16(c[mi][2], a[mi], b[1][0], b[1][1]);
                mma_f16(c[mi][3], a[mi], b[1][2], b[1][3]);
            }
        }
        cur = (cur + 1) % 3;
    }

    const int fr = lane >> 2, fc2 = (lane & 3) * 2;
#pragma unroll
    for (int mi = 0; mi < 4; mi++) {
        int r1 = wm + mi * 16 + fr;
        int m1 = m0 + r1, m2 = m1 + 8;
#pragma unroll
        for (int ni = 0; ni < 4; ni++) {
            int col = n0 + wn + ni * 8 + fc2;
            if (m1 < cnt)
                *reinterpret_cast<float2*>(&g_O[(size_t)(off+m1) * HDIM + col]) =
                    make_float2(c[mi][ni][0], c[mi][ni][1]);
            if (m2 < cnt)
                *reinterpret_cast<float2*>(&g_O[(size_t)(off+m2) * HDIM + col]) =
                    make_float2(c[mi][ni][2], c[mi][ni][3]);
        }
    }
}

// ---------------- combine + losses ----------------
__global__ void combine_kernel(float* __restrict__ out) {
    int idx = blockIdx.x * blockDim.x + threadIdx.x;
    int t = idx >> 8;
    int c4 = idx & 255;
    if (t >= TOKENS) return;
    int s0 = g_slot_of[t*2], s1 = g_slot_of[t*2+1];
    float w0 = g_score[t*2], w1 = g_score[t*2+1];
    float4 a = *reinterpret_cast<const float4*>(&g_O[(size_t)s0 * HDIM + c4*4]);
    float4 b = *reinterpret_cast<const float4*>(&g_O[(size_t)s1 * HDIM + c4*4]);
    float4 o;
    o.x = w0*a.x + w1*b.x; o.y = w0*a.y + w1*b.y;
    o.z = w0*a.z + w1*b.z; o.w = w0*a.w + w1*b.w;
    *reinterpret_cast<float4*>(&out[(size_t)t * HDIM + c4*4]) = o;
}

__global__ void loss_kernel(float* __restrict__ out) {
    int lane = threadIdx.x;
    float z = 0.f, pe[NEXP];
#pragma unroll
    for (int e = 0; e < NEXP; e++) pe[e] = 0.f;
    for (int i = lane; i < RBLOCKS; i += 32) {
        z += g_zpart[i];
#pragma unroll
        for (int e = 0; e < NEXP; e++) pe[e] += g_ppart[i*NEXP + e];
    }
#pragma unroll
    for (int o = 16; o > 0; o >>= 1) {
        z += __shfl_xor_sync(0xffffffffu, z, o);
#pragma unroll
        for (int e = 0; e < NEXP; e++) pe[e] += __shfl_xor_sync(0xffffffffu, pe[e], o);
    }
    if (lane == 0) {
        float zl = (float)NEXP * (z / (float)((size_t)TOKENS * NEXP));
        float aux = 0.f;
#pragma unroll
        for (int e = 0; e < NEXP; e++) {
            float pm = pe[e] / (float)TOKENS;
            aux += pm * logf(pm + 1e-9f);
        }
        out[(size_t)TOKENS * HDIM    ] = zl;
        out[(size_t)TOKENS * HDIM + 1] = (float)NEXP * aux;
    }
}

// ---------------- launch ----------------
extern "C" void kernel_launch(void* const* d_in, const int* in_sizes, int n_in,
                              void* d_out, int out_size) {
    const float* x        = (const float*)d_in[0];
    const float* w_router = (const float*)d_in[1];
    const float* w_gate   = (const float*)d_in[2];
    const float* w_up     = (const float*)d_in[3];
    const float* w_down   = (const float*)d_in[4];
    float* out = (float*)d_out;

    cudaFuncSetAttribute(gemm1_kernel, cudaFuncAttributeMaxDynamicSharedMemorySize, G1_SMEM);
    cudaFuncSetAttribute(gemm2_kernel, cudaFuncAttributeMaxDynamicSharedMemorySize, G2_SMEM);

    router_kernel<<<RBLOCKS, 256>>>(x, w_router);                               // 1
    route_kernel<<<1, 1024>>>();                                                // 2
    convert_w_kernel<<<dim3(2048, 1, 24), dim3(32, 8)>>>(w_gate, w_up, w_down); // 3
    gemm1_kernel<<<dim3(FFDIM/64, 64, NEXP), 256, G1_SMEM>>>();                 // 4 <- profiled
    gemm2_kernel<<<dim3(HDIM/128, 64, NEXP), 256, G2_SMEM>>>();                 // 5
    combine_kernel<<<(TOKENS*256)/256, 256>>>(out);                             // 6
    loss_kernel<<<1, 32>>>(out);                                                // 7
}